// round 11
// baseline (speedup 1.0000x reference)
#include <cuda_runtime.h>
#include <math.h>

#define N_NODES_MAX 50000
#define N_EDGES_MAX 800000
#define HDIM 64
#define N_GRAPHS 64

// Scratch (device globals — allocation-free, referenced directly in kernels)
__device__ __align__(16) float g_h[N_NODES_MAX * HDIM];     // 12.8 MB (layer-1 lin)
__device__ __align__(16) float g_h2[N_NODES_MAX * HDIM];    // 12.8 MB (layer-2 lin)
__device__ __align__(16) float g_gsum[N_GRAPHS * HDIM];
__device__ __align__(16) float g_gcnt[N_GRAPHS];
__device__ __align__(16) int g_deg[N_NODES_MAX + 4];
__device__ __align__(16) int g_rowptr[N_NODES_MAX + 4];
__device__ __align__(16) int g_rank[N_EDGES_MAX + 4];
__device__ __align__(16) int g_col[N_EDGES_MAX];

// ---------------------------------------------------------------------------
// Zero degree histogram + pool accumulators
// ---------------------------------------------------------------------------
__global__ void zero_small_kernel(int N) {
    int i = blockIdx.x * blockDim.x + threadIdx.x;
    if (i <= N)               g_deg[i]  = 0;
    if (i < N_GRAPHS * HDIM)  g_gsum[i] = 0.f;
    if (i < N_GRAPHS)         g_gcnt[i] = 0.f;
}

// ---------------------------------------------------------------------------
// CSR build: hist captures per-edge rank from the atomic return value,
// so fill is atomic-free.
// ---------------------------------------------------------------------------
__global__ void hist_kernel(const int* __restrict__ ei, int E) {
    int e = (blockIdx.x * blockDim.x + threadIdx.x) * 4;
    if (e + 3 < E) {
        int4 d = *(const int4*)(ei + E + e);
        int4 r;
        r.x = atomicAdd(&g_deg[d.x], 1);
        r.y = atomicAdd(&g_deg[d.y], 1);
        r.z = atomicAdd(&g_deg[d.z], 1);
        r.w = atomicAdd(&g_deg[d.w], 1);
        *(int4*)(g_rank + e) = r;
    } else {
        for (int j = e; j < E; ++j)
            g_rank[j] = atomicAdd(&g_deg[__ldg(&ei[E + j])], 1);
    }
}

// Single-block exclusive scan of g_deg[0..N) -> g_rowptr
__global__ void scan_kernel(int N) {
    __shared__ int wsum[32];
    __shared__ int s_carry;
    int tid = threadIdx.x, lane = tid & 31, wid = tid >> 5;
    if (tid == 0) s_carry = 0;
    __syncthreads();
    const int CHUNK = 4096;
    for (int base = 0; base < N; base += CHUNK) {
        int i0 = base + tid * 4;
        int v0 = 0, v1 = 0, v2 = 0, v3 = 0;
        if (i0 + 3 < N) {
            int4 v = *(const int4*)(g_deg + i0);
            v0 = v.x; v1 = v.y; v2 = v.z; v3 = v.w;
        } else {
            if (i0     < N) v0 = g_deg[i0];
            if (i0 + 1 < N) v1 = g_deg[i0 + 1];
            if (i0 + 2 < N) v2 = g_deg[i0 + 2];
            if (i0 + 3 < N) v3 = g_deg[i0 + 3];
        }
        int tsum = v0 + v1 + v2 + v3;
        int x = tsum;
#pragma unroll
        for (int o = 1; o < 32; o <<= 1) {
            int y = __shfl_up_sync(0xffffffffu, x, o);
            if (lane >= o) x += y;
        }
        if (lane == 31) wsum[wid] = x;
        __syncthreads();
        if (wid == 0) {
            int t = wsum[lane];
#pragma unroll
            for (int o = 1; o < 32; o <<= 1) {
                int y = __shfl_up_sync(0xffffffffu, t, o);
                if (lane >= o) t += y;
            }
            wsum[lane] = t;
        }
        __syncthreads();
        int excl = x - tsum + (wid > 0 ? wsum[wid - 1] : 0) + s_carry;
        if (i0     < N) g_rowptr[i0]     = excl;
        if (i0 + 1 < N) g_rowptr[i0 + 1] = excl + v0;
        if (i0 + 2 < N) g_rowptr[i0 + 2] = excl + v0 + v1;
        if (i0 + 3 < N) g_rowptr[i0 + 3] = excl + v0 + v1 + v2;
        int total = wsum[31];
        __syncthreads();
        if (tid == 0) s_carry += total;
        __syncthreads();
    }
    if (tid == 0) g_rowptr[N] = s_carry;
}

// Atomic-free fill: g_col[rowptr[dst] + rank[e]] = src
__global__ void fill_kernel(const int* __restrict__ ei, int E) {
    int e = (blockIdx.x * blockDim.x + threadIdx.x) * 4;
    if (e + 3 < E) {
        int4 s = *(const int4*)(ei + e);
        int4 d = *(const int4*)(ei + E + e);
        int4 r = *(const int4*)(g_rank + e);
        g_col[__ldg(&g_rowptr[d.x]) + r.x] = s.x;
        g_col[__ldg(&g_rowptr[d.y]) + r.y] = s.y;
        g_col[__ldg(&g_rowptr[d.z]) + r.z] = s.z;
        g_col[__ldg(&g_rowptr[d.w]) + r.w] = s.w;
    } else {
        for (int j = e; j < E; ++j)
            g_col[__ldg(&g_rowptr[__ldg(&ei[E + j])]) + g_rank[j]] = __ldg(&ei[j]);
    }
}

// ---------------------------------------------------------------------------
// Warp-cooperative gather of one node's in-edge sum from src[].
// Half-warp per edge, float4 per lane (2 edges per warp-instruction).
// Returns combined float4 (valid in half==0 lanes after the xor-combine).
// ---------------------------------------------------------------------------
__device__ __forceinline__ float4 warp_gather_node(
    const float4* __restrict__ hp, int beg, int end,
    int lane, int half, int hl) {
    float4 acc = {0.f, 0.f, 0.f, 0.f};
    int i = beg;
    while (i < end) {
        int m = min(32, end - i);
        int c = (lane < m) ? __ldg(&g_col[i + lane]) : 0;
        int j = 0;
        for (; j + 8 <= m; j += 8) {
            int s0 = __shfl_sync(0xffffffffu, c, j     + half);
            int s1 = __shfl_sync(0xffffffffu, c, j + 2 + half);
            int s2 = __shfl_sync(0xffffffffu, c, j + 4 + half);
            int s3 = __shfl_sync(0xffffffffu, c, j + 6 + half);
            float4 v0 = hp[s0 * 16 + hl];
            float4 v1 = hp[s1 * 16 + hl];
            float4 v2 = hp[s2 * 16 + hl];
            float4 v3 = hp[s3 * 16 + hl];
            acc.x += (v0.x + v1.x) + (v2.x + v3.x);
            acc.y += (v0.y + v1.y) + (v2.y + v3.y);
            acc.z += (v0.z + v1.z) + (v2.z + v3.z);
            acc.w += (v0.w + v1.w) + (v2.w + v3.w);
        }
        for (; j < m; j += 2) {
            int idx = j + half;
            bool valid = idx < m;
            int s = __shfl_sync(0xffffffffu, c, valid ? idx : m - 1);
            float4 v = hp[s * 16 + hl];
            if (valid) {
                acc.x += v.x; acc.y += v.y; acc.z += v.z; acc.w += v.w;
            }
        }
        i += m;
    }
    acc.x += __shfl_xor_sync(0xffffffffu, acc.x, 16);
    acc.y += __shfl_xor_sync(0xffffffffu, acc.y, 16);
    acc.z += __shfl_xor_sync(0xffffffffu, acc.z, 16);
    acc.w += __shfl_xor_sync(0xffffffffu, acc.w, 16);
    return acc;
}

// ---------------------------------------------------------------------------
// FUSED layer-2: per block of 128 nodes:
//   phase 1: xs[n][:] = relu(gather(g_h, n) + b1)      (gather -> smem)
//   phase 2: g_h2[n][:] = xs[n][:] @ W2                 (register-tiled GEMM)
// W2 staged at kernel start (overlaps gather loads).
// ---------------------------------------------------------------------------
__global__ void __launch_bounds__(256, 4)
fused_gather_gemm(const float* __restrict__ W2,
                  const float* __restrict__ b1, int N) {
    const int XS = 68;                       // row stride: 16B aligned, +4 pad
    __shared__ float  xs[128 * XS];          // 34.8 KB
    __shared__ float4 ws[64 * 16];           // 16 KB

    int tid  = threadIdx.x;
    int wid  = tid >> 5;
    int lane = tid & 31;
    int half = lane >> 4;
    int hl   = lane & 15;
    int row0 = blockIdx.x * 128;

    // Stage W2 (64x64 = 1024 float4)
#pragma unroll
    for (int j = 0; j < 4; ++j) {
        int id = tid + 256 * j;
        ws[id] = ((const float4*)W2)[id];
    }

    // Phase 1: each warp gathers 16 nodes into smem
    const float4* hp = (const float4*)g_h;
    float4 b1v = ((const float4*)b1)[hl];
#pragma unroll 1
    for (int t = 0; t < 16; ++t) {
        int r = wid * 16 + t;
        int n = row0 + r;
        if (n >= N) break;
        int beg = __ldg(&g_rowptr[n]);
        int end = __ldg(&g_rowptr[n + 1]);
        float4 acc = warp_gather_node(hp, beg, end, lane, half, hl);
        if (half == 0) {
            float4 o;
            o.x = fmaxf(acc.x + b1v.x, 0.f);
            o.y = fmaxf(acc.y + b1v.y, 0.f);
            o.z = fmaxf(acc.z + b1v.z, 0.f);
            o.w = fmaxf(acc.w + b1v.w, 0.f);
            *(float4*)&xs[r * XS + hl * 4] = o;
        }
    }
    __syncthreads();

    // Phase 2: register-tiled GEMM from smem (K = 64)
    int cg = tid & 15;
    int rt = tid >> 4;
    float4 acc[8];
#pragma unroll
    for (int i = 0; i < 8; ++i) acc[i] = make_float4(0.f, 0.f, 0.f, 0.f);

#pragma unroll
    for (int kk = 0; kk < 64; ++kk) {
        float4 w = ws[kk * 16 + cg];
#pragma unroll
        for (int i = 0; i < 8; ++i) {
            float xv = xs[(rt * 8 + i) * XS + kk];
            acc[i].x += xv * w.x;
            acc[i].y += xv * w.y;
            acc[i].z += xv * w.z;
            acc[i].w += xv * w.w;
        }
    }

#pragma unroll
    for (int i = 0; i < 8; ++i) {
        int row = row0 + rt * 8 + i;
        if (row < N)
            ((float4*)&g_h2[row * HDIM])[cg] = acc[i];
    }
}

// ---------------------------------------------------------------------------
// Gather + mean-pool stage 1 (layer 2 aggregate): one warp per node,
// v = relu(gather(g_h2) + b2); float4 red into g_gsum[batch[n]].
// ---------------------------------------------------------------------------
__global__ void __launch_bounds__(256, 8)
gather_pool_kernel(const float* __restrict__ b2,
                   const int* __restrict__ batch, int N) {
    int w = (blockIdx.x * blockDim.x + threadIdx.x) >> 5;
    if (w >= N) return;
    int lane = threadIdx.x & 31;
    int half = lane >> 4;
    int hl   = lane & 15;
    int beg = __ldg(&g_rowptr[w]);
    int end = __ldg(&g_rowptr[w + 1]);

    float4 acc = warp_gather_node((const float4*)g_h2, beg, end, lane, half, hl);

    if (half == 0) {
        float4 b = ((const float4*)b2)[hl];
        float4 o;
        o.x = fmaxf(acc.x + b.x, 0.f);
        o.y = fmaxf(acc.y + b.y, 0.f);
        o.z = fmaxf(acc.z + b.z, 0.f);
        o.w = fmaxf(acc.w + b.w, 0.f);
        int g = __ldg(&batch[w]);
        atomicAdd((float4*)(g_gsum + g * HDIM + hl * 4), o);
        if (hl == 0) atomicAdd(&g_gcnt[g], 1.0f);
    }
}

// ---------------------------------------------------------------------------
// Layer-1 GEMM: g_h[n,64] = X[n,:128] @ W1[128,64]  (register-tiled)
// ---------------------------------------------------------------------------
__global__ void gemm_nodes1(const float* __restrict__ X,
                            const float* __restrict__ Wg,
                            int N) {
    const int K = 128, KC = 32;
    __shared__ float  xs[128][KC + 1];
    __shared__ float4 ws[KC][16];

    int tid = threadIdx.x;
    int cg  = tid & 15;
    int rt  = tid >> 4;
    int row0 = blockIdx.x * 128;

    float4 acc[8];
#pragma unroll
    for (int i = 0; i < 8; ++i) acc[i] = make_float4(0.f, 0.f, 0.f, 0.f);

    for (int kc = 0; kc < K; kc += KC) {
#pragma unroll
        for (int j = 0; j < 2; ++j) {
            int id = tid + 256 * j;
            int k = id >> 4, c = id & 15;
            ws[k][c] = ((const float4*)Wg)[(kc + k) * 16 + c];
        }
#pragma unroll
        for (int j = 0; j < 4; ++j) {
            int q = tid + 256 * j;
            int r = q >> 3, c4 = q & 7;
            int row = row0 + r;
            float4 v = make_float4(0.f, 0.f, 0.f, 0.f);
            if (row < N)
                v = *(const float4*)(X + row * K + kc + c4 * 4);
            xs[r][c4 * 4]     = v.x;
            xs[r][c4 * 4 + 1] = v.y;
            xs[r][c4 * 4 + 2] = v.z;
            xs[r][c4 * 4 + 3] = v.w;
        }
        __syncthreads();

#pragma unroll
        for (int kk = 0; kk < KC; ++kk) {
            float4 w = ws[kk][cg];
#pragma unroll
            for (int i = 0; i < 8; ++i) {
                float xv = xs[rt * 8 + i][kk];
                acc[i].x += xv * w.x;
                acc[i].y += xv * w.y;
                acc[i].z += xv * w.z;
                acc[i].w += xv * w.w;
            }
        }
        __syncthreads();
    }

#pragma unroll
    for (int i = 0; i < 8; ++i) {
        int row = row0 + rt * 8 + i;
        if (row < N)
            ((float4*)&g_h[row * HDIM])[cg] = acc[i];
    }
}

// ---------------------------------------------------------------------------
// Head: pooled -> fc1(relu) -> fc2 -> log_softmax. One thread per graph.
// ---------------------------------------------------------------------------
__global__ void head_kernel(const float* __restrict__ fc1w,
                            const float* __restrict__ fc1b,
                            const float* __restrict__ fc2w,
                            const float* __restrict__ fc2b,
                            float* __restrict__ out) {
    int g = threadIdx.x;
    if (g >= N_GRAPHS) return;

    float inv = 1.0f / fmaxf(g_gcnt[g], 1.0f);
    float p[HDIM];
#pragma unroll
    for (int c = 0; c < HDIM; ++c) p[c] = g_gsum[g * HDIM + c] * inv;

    float z1[32];
#pragma unroll
    for (int j = 0; j < 32; ++j) {
        float s = fc1b[j];
#pragma unroll
        for (int c = 0; c < HDIM; ++c) s += p[c] * fc1w[c * 32 + j];
        z1[j] = fmaxf(s, 0.f);
    }

    float z2[10];
    float m = -1e30f;
#pragma unroll
    for (int k = 0; k < 10; ++k) {
        float s = fc2b[k];
#pragma unroll
        for (int j = 0; j < 32; ++j) s += z1[j] * fc2w[j * 10 + k];
        z2[k] = s;
        m = fmaxf(m, s);
    }
    float se = 0.f;
#pragma unroll
    for (int k = 0; k < 10; ++k) se += expf(z2[k] - m);
    float lse = m + logf(se);
#pragma unroll
    for (int k = 0; k < 10; ++k) out[g * 10 + k] = z2[k] - lse;
}

// ---------------------------------------------------------------------------
// Launch — capturable ops only. Streams/events lazily created OUTSIDE capture.
// ---------------------------------------------------------------------------
static cudaStream_t s_side = 0;
static cudaEvent_t  s_ev_fork = 0, s_ev_join = 0;

extern "C" void kernel_launch(void* const* d_in, const int* in_sizes, int n_in,
                              void* d_out, int out_size) {
    const float* x     = (const float*)d_in[0];
    const int*   ei    = (const int*)d_in[1];    // int32
    const int*   batch = (const int*)d_in[2];    // int32
    const float* W1    = (const float*)d_in[3];
    const float* b1    = (const float*)d_in[4];
    const float* W2    = (const float*)d_in[5];
    const float* b2    = (const float*)d_in[6];
    const float* fc1w  = (const float*)d_in[7];
    const float* fc1b  = (const float*)d_in[8];
    const float* fc2w  = (const float*)d_in[9];
    const float* fc2b  = (const float*)d_in[10];
    float* out = (float*)d_out;

    int N = in_sizes[0] / 128;   // nodes
    int E = in_sizes[1] / 2;     // edges

    if (!s_side) {
        cudaStreamCreateWithFlags(&s_side, cudaStreamNonBlocking);
        cudaEventCreateWithFlags(&s_ev_fork, cudaEventDisableTiming);
        cudaEventCreateWithFlags(&s_ev_join, cudaEventDisableTiming);
    }

    int gemm_blocks   = (N + 127) / 128;
    int edge4_blocks  = (E / 4 + 255) / 256 + 1;
    int gather_blocks = (N * 32 + 255) / 256;

    // Fork: CSR build on side stream, concurrent with gemm1 on main stream
    cudaEventRecord(s_ev_fork, 0);
    cudaStreamWaitEvent(s_side, s_ev_fork, 0);

    zero_small_kernel<<<(N + 256) / 256, 256, 0, s_side>>>(N);
    hist_kernel<<<edge4_blocks, 256, 0, s_side>>>(ei, E);
    scan_kernel<<<1, 1024, 0, s_side>>>(N);
    fill_kernel<<<edge4_blocks, 256, 0, s_side>>>(ei, E);
    cudaEventRecord(s_ev_join, s_side);

    // Main stream: gemm1 overlaps the build
    gemm_nodes1<<<gemm_blocks, 256>>>(x, W1, N);

    // Join: fused layer-2 needs g_h and the CSR
    cudaStreamWaitEvent(0, s_ev_join, 0);

    // Fused: g_h2 = relu(gather(g_h) + b1) @ W2
    fused_gather_gemm<<<gemm_blocks, 256>>>(W2, b1, N);

    // Layer-2 aggregate + pool: gsum += relu(gather(g_h2) + b2)
    gather_pool_kernel<<<gather_blocks, 256>>>(b2, batch, N);

    // Head
    head_kernel<<<1, 64>>>(fc1w, fc1b, fc2w, fc2b, out);
}